// round 2
// baseline (speedup 1.0000x reference)
#include <cuda_runtime.h>

// B=2048, D=3706, total=B*D=7,589,888 (divisible by 256)
// inputs: d_in[0] fake [B,D] f32; d_in[1] minb [D] f32; d_in[2] lens [D,4] f32
// output: dist f32 [B,D,6] then val f32 [B,D]
//
// b0=min[d]; b_{k+1}=b_k+relu(len[d,k])+1e-4 (strictly increasing)
// dist[r] = (r==0 || a>b[r-1]) && (r==5 || a<b[r]); a==b_k -> all zeros
// val = sum r*dist[r]
//
// R2: stage dist in smem, flush as coalesced float4 stores (fixes the
// 24B-stride STG.64 wavefront blowup seen in R1 ncu: L1=58.6% > DRAM=53.7%).

#define EPSK 1e-4f
#define TPB 256

__global__ void __launch_bounds__(TPB)
discret_kernel(const float* __restrict__ fake,
               const float* __restrict__ minb,
               const float4* __restrict__ lens,
               float* __restrict__ out_dist,   // [B*D*6]
               float* __restrict__ out_val,    // [B*D]
               int total, int D)
{
    __shared__ float sdist[TPB * 6];   // 6 KB

    int t   = threadIdx.x;
    int idx = blockIdx.x * TPB + t;

    float d0 = 0.f, d1 = 0.f, d2 = 0.f, d3 = 0.f, d4 = 0.f, d5 = 0.f;
    bool valid = (idx < total);

    if (valid) {
        int d = idx % D;

        float a  = fake[idx];
        float4 L = __ldg(&lens[d]);
        float b0 = __ldg(&minb[d]);
        float b1 = b0 + fmaxf(L.x, 0.0f) + EPSK;
        float b2 = b1 + fmaxf(L.y, 0.0f) + EPSK;
        float b3 = b2 + fmaxf(L.z, 0.0f) + EPSK;
        float b4 = b3 + fmaxf(L.w, 0.0f) + EPSK;

        d0 = (a < b0)           ? 1.0f : 0.0f;
        d1 = (a > b0 && a < b1) ? 1.0f : 0.0f;
        d2 = (a > b1 && a < b2) ? 1.0f : 0.0f;
        d3 = (a > b2 && a < b3) ? 1.0f : 0.0f;
        d4 = (a > b3 && a < b4) ? 1.0f : 0.0f;
        d5 = (a > b4)           ? 1.0f : 0.0f;

        out_val[idx] = d1 + 2.0f * d2 + 3.0f * d3 + 4.0f * d4 + 5.0f * d5;
    }

    // stage into smem (stride-6 word writes: benign 2-way bank conflict)
    float* s = sdist + t * 6;
    s[0] = d0; s[1] = d1; s[2] = d2; s[3] = d3; s[4] = d4; s[5] = d5;
    __syncthreads();

    int block_first = blockIdx.x * TPB;
    int n_valid = total - block_first;
    if (n_valid >= TPB) {
        // full block: flush 1536 floats = 384 float4, fully coalesced
        const float4* s4 = reinterpret_cast<const float4*>(sdist);
        float4* g4 = reinterpret_cast<float4*>(out_dist + (size_t)block_first * 6);
        #pragma unroll
        for (int i = t; i < (TPB * 6) / 4; i += TPB)
            g4[i] = s4[i];
    } else {
        // tail block (unused for this shape, kept for generality)
        float* g = out_dist + (size_t)block_first * 6;
        for (int i = t; i < n_valid * 6; i += TPB)
            g[i] = sdist[i];
    }
}

extern "C" void kernel_launch(void* const* d_in, const int* in_sizes, int n_in,
                              void* d_out, int out_size)
{
    const float*  fake = (const float*)d_in[0];
    const float*  minb = (const float*)d_in[1];
    const float4* lens = (const float4*)d_in[2];

    int total = in_sizes[0];          // B*D
    int D     = in_sizes[1];          // 3706

    float* out  = (float*)d_out;
    float* dist = out;                          // [B*D*6]
    float* val  = out + (size_t)total * 6;      // [B*D]

    int blocks = (total + TPB - 1) / TPB;
    discret_kernel<<<blocks, TPB>>>(fake, minb, lens, dist, val, total, D);
}